// round 2
// baseline (speedup 1.0000x reference)
#include <cuda_runtime.h>
#include <cuda_fp16.h>
#include <cstdint>
#include <cstddef>

#define S_TOT  262144
#define NBLK   2048          // S_TOT / 128
#define NUSERS 1000000
#define SQRT192 13.856406460551018f

// ---------------- static device scratch (no cudaMalloc allowed) ----------------
__device__ __half g_BT[2][128][128];   // [type][n][k] fp16 weights (type 0=ssl,1=rs)
__device__ float  g_cvec[2][128];      // rowsum of W1[:, :64]  (loss coefficient)
__device__ float  g_bias1[2][128];
__device__ float  g_w2[2][128];
__device__ float  g_scal[6];           // b_ssl2, b_rs2, b_ssl3, b_rs3, prelu_a
__device__ float  g_z[12L * S_TOT];    // 12 pre-BN streams
__device__ float  g_psum[12 * NBLK];
__device__ float  g_psq [12 * NBLK];
__device__ float2 g_mi[12];            // (mean, inv_std) per stream

// ---------------- kernel 0: pack weights ----------------
__global__ void prep_kernel(
    const float* __restrict__ Wssl1, const float* __restrict__ bssl1,
    const float* __restrict__ Wssl2, const float* __restrict__ bssl2,
    const float* __restrict__ Wssl3, const float* __restrict__ bssl3,
    const float* __restrict__ Wrs1,  const float* __restrict__ brs1,
    const float* __restrict__ Wrs2,  const float* __restrict__ brs2,
    const float* __restrict__ Wrs3,  const float* __restrict__ brs3,
    const float* __restrict__ pa)
{
    int t = threadIdx.x;
    // BT[type][n][k]: n<96 -> W1[n][64+k] ; n==96 -> z3 weight vector ; else 0
    for (int idx = t; idx < 2 * 128 * 128; idx += 256) {
        int ty = idx >> 14;
        int n  = (idx >> 7) & 127;
        int k  = idx & 127;
        const float* W1 = ty ? Wrs1 : Wssl1;
        float v = 0.f;
        if (n < 96) {
            v = W1[n * 192 + 64 + k];
        } else if (n == 96) {
            v = ty ? ((k < 64) ? Wrs3[k] : 0.f) : Wssl3[k];
        }
        g_BT[ty][n][k] = __float2half_rn(v);
    }
    // per-column epilogue constants
    {
        int ty = t >> 7, n = t & 127;
        const float* W1 = ty ? Wrs1 : Wssl1;
        float c = 0.f, b = 0.f, w = 0.f;
        if (n < 96) {
            for (int k = 0; k < 64; k++) c += W1[n * 192 + k];
            b = (ty ? brs1 : bssl1)[n];
            w = (ty ? Wrs2 : Wssl2)[n];
        }
        g_cvec[ty][n]  = c;
        g_bias1[ty][n] = b;
        g_w2[ty][n]    = w;
    }
    if (t == 0) {
        g_scal[0] = bssl2[0]; g_scal[1] = brs2[0];
        g_scal[2] = bssl3[0]; g_scal[3] = brs3[0];
        g_scal[4] = pa[0];
    }
}

// ---------------- kernel 1: gather + HMMA + epilogue ----------------
__global__ __launch_bounds__(256, 2)
void mwn_main(const float* __restrict__ infoNCE, const float* __restrict__ bloss,
              const int* __restrict__ stepIdx,  const int* __restrict__ uIdxList,
              const float* __restrict__ uembeds, const float* __restrict__ uembed)
{
    __shared__ __half sX[128 * 136];      // [sample][k], stride 136 halves (bank-safe)
    __shared__ float  sLoss[128];
    __shared__ int    sIdx[128];
    __shared__ float  sC[128], sB1[128], sW2[128];
    __shared__ float  sZ1[128], sZ3[128];
    __shared__ float  sRed[16];

    const int t = threadIdx.x, lane = t & 31, w = t >> 5;
    const int combo = blockIdx.y;
    const int type  = combo >= 3 ? 1 : 0;
    const int beh   = combo - 3 * type;
    const int s0    = blockIdx.x * 128;

    if (t < 128) {
        int s = s0 + t;
        if (type == 0) { sIdx[t] = stepIdx[s];               sLoss[t] = infoNCE[beh * S_TOT + s]; }
        else           { sIdx[t] = uIdxList[beh * S_TOT + s]; sLoss[t] = bloss[beh * S_TOT + s]; }
    } else {
        int n = t - 128;
        sC[n]  = g_cvec[type][n];
        sB1[n] = g_bias1[type][n];
        sW2[n] = g_w2[type][n];
    }
    __syncthreads();

    // gather: 128 rows x 128 floats; 1 warp = 1 full row per iteration (2x256B segments)
    #pragma unroll
    for (int it = 0; it < 16; ++it) {
        int lid = it * 256 + t;
        int r = lid >> 5, f = lid & 31;
        int idx = sIdx[r];
        size_t eo = ((size_t)beh * NUSERS + (size_t)idx) * 64;
        size_t uo = (size_t)idx * 64;
        const float* srcA = type ? (uembed + uo)  : (uembeds + eo);  // k 0..63
        const float* srcB = type ? (uembeds + eo) : (uembed + uo);   // k 64..127
        const float4* p = (f < 16) ? ((const float4*)srcA + f)
                                   : ((const float4*)srcB + (f - 16));
        float4 v = __ldg(p);
        int k = f * 4;
        *(__half2*)&sX[r * 136 + k]     = __floats2half2_rn(v.x, v.y);
        *(__half2*)&sX[r * 136 + k + 2] = __floats2half2_rn(v.z, v.w);
    }
    __syncthreads();

    // ---- MMA: each warp owns a 16-row slab; A (16x128) resident in registers ----
    const int g = lane >> 2, tg = lane & 3;
    uint32_t a[8][4];
    {
        uint32_t base = (uint32_t)__cvta_generic_to_shared(sX);
        int mat = lane >> 3, rowin = lane & 7;
        uint32_t arow = (uint32_t)(w * 16 + (mat & 1) * 8 + rowin);
        uint32_t aoff = base + (arow * 136 + (mat >> 1) * 8) * 2;
        #pragma unroll
        for (int ks = 0; ks < 8; ++ks) {
            asm volatile("ldmatrix.sync.aligned.m8n8.x4.shared.b16 {%0,%1,%2,%3}, [%4];"
                : "=r"(a[ks][0]), "=r"(a[ks][1]), "=r"(a[ks][2]), "=r"(a[ks][3])
                : "r"(aoff + ks * 32));
        }
    }
    const float l0 = sLoss[w * 16 + g], l1 = sLoss[w * 16 + 8 + g];
    const float pa = g_scal[4], b2 = g_scal[type], b3 = g_scal[2 + type];
    float zacc0 = 0.f, zacc1 = 0.f, y96a = 0.f, y96b = 0.f;

    #pragma unroll
    for (int nt = 0; nt < 13; ++nt) {
        float c0 = 0.f, c1 = 0.f, c2 = 0.f, c3 = 0.f;
        const __half* Brow = &g_BT[type][nt * 8 + g][0];
        #pragma unroll
        for (int ks = 0; ks < 8; ++ks) {
            uint32_t b0 = *(const uint32_t*)(Brow + ks * 16 + tg * 2);
            uint32_t b1 = *(const uint32_t*)(Brow + ks * 16 + tg * 2 + 8);
            asm volatile("mma.sync.aligned.m16n8k16.row.col.f32.f16.f16.f32 "
                "{%0,%1,%2,%3}, {%4,%5,%6,%7}, {%8,%9}, {%0,%1,%2,%3};"
                : "+f"(c0), "+f"(c1), "+f"(c2), "+f"(c3)
                : "r"(a[ks][0]), "r"(a[ks][1]), "r"(a[ks][2]), "r"(a[ks][3]),
                  "r"(b0), "r"(b1));
        }
        if (nt < 12) {
            int n0 = nt * 8 + tg * 2;
            float cA = sC[n0], cB = sC[n0 + 1];
            float bA = sB1[n0], bB = sB1[n0 + 1];
            float wA = sW2[n0], wB = sW2[n0 + 1];
            float h;
            h = fmaf(l0, cA, c0) + bA; h = h >= 0.f ? h : pa * h; zacc0 = fmaf(h, wA, zacc0);
            h = fmaf(l0, cB, c1) + bB; h = h >= 0.f ? h : pa * h; zacc0 = fmaf(h, wB, zacc0);
            h = fmaf(l1, cA, c2) + bA; h = h >= 0.f ? h : pa * h; zacc1 = fmaf(h, wA, zacc1);
            h = fmaf(l1, cB, c3) + bB; h = h >= 0.f ? h : pa * h; zacc1 = fmaf(h, wB, zacc1);
        } else if (tg == 0) {
            y96a = c0;   // y[96] for row w*16+g
            y96b = c2;   // y[96] for row w*16+8+g
        }
    }
    zacc0 += __shfl_xor_sync(~0u, zacc0, 1); zacc0 += __shfl_xor_sync(~0u, zacc0, 2);
    zacc1 += __shfl_xor_sync(~0u, zacc1, 1); zacc1 += __shfl_xor_sync(~0u, zacc1, 2);
    if (tg == 0) {
        sZ1[w * 16 + g]     = SQRT192 * (zacc0 + b2);
        sZ1[w * 16 + 8 + g] = SQRT192 * (zacc1 + b2);
        float z3;
        z3 = fmaf(l0, y96a, b3); z3 = z3 >= 0.f ? z3 : pa * z3; sZ3[w * 16 + g]     = z3;
        z3 = fmaf(l1, y96b, b3); z3 = z3 >= 0.f ? z3 : pa * z3; sZ3[w * 16 + 8 + g] = z3;
    }
    __syncthreads();

    // ---- write z streams + deterministic per-block stats partials ----
    if (t < 128) {
        float z1 = sZ1[t], z3 = sZ3[t];
        int s = s0 + t;
        g_z[(size_t)(combo * 2)     * S_TOT + s] = z1;
        g_z[(size_t)(combo * 2 + 1) * S_TOT + s] = z3;
        float s1 = z1, q1 = z1 * z1, s3 = z3, q3 = z3 * z3;
        #pragma unroll
        for (int o = 16; o; o >>= 1) {
            s1 += __shfl_down_sync(~0u, s1, o); q1 += __shfl_down_sync(~0u, q1, o);
            s3 += __shfl_down_sync(~0u, s3, o); q3 += __shfl_down_sync(~0u, q3, o);
        }
        if (lane == 0) {
            sRed[w * 4]     = s1; sRed[w * 4 + 1] = q1;
            sRed[w * 4 + 2] = s3; sRed[w * 4 + 3] = q3;
        }
    }
    __syncthreads();
    if (t == 0) {
        float s1 = sRed[0] + sRed[4] + sRed[8]  + sRed[12];
        float q1 = sRed[1] + sRed[5] + sRed[9]  + sRed[13];
        float s3 = sRed[2] + sRed[6] + sRed[10] + sRed[14];
        float q3 = sRed[3] + sRed[7] + sRed[11] + sRed[15];
        int st1 = combo * 2, st3 = combo * 2 + 1;
        g_psum[st1 * NBLK + blockIdx.x] = s1; g_psq[st1 * NBLK + blockIdx.x] = q1;
        g_psum[st3 * NBLK + blockIdx.x] = s3; g_psq[st3 * NBLK + blockIdx.x] = q3;
    }
}

// ---------------- kernel 2: deterministic stats reduce ----------------
__global__ void reduce_kernel()
{
    int st = blockIdx.x, t = threadIdx.x;
    float s = 0.f, q = 0.f;
    for (int i = t; i < NBLK; i += 256) {
        s += g_psum[st * NBLK + i];
        q += g_psq [st * NBLK + i];
    }
    __shared__ float ss[256], sq[256];
    ss[t] = s; sq[t] = q;
    __syncthreads();
    for (int o = 128; o; o >>= 1) {
        if (t < o) { ss[t] += ss[t + o]; sq[t] += sq[t + o]; }
        __syncthreads();
    }
    if (t == 0) {
        float m = ss[0] / (float)S_TOT;
        float v = sq[0] / (float)S_TOT - m * m;
        if (v < 0.f) v = 0.f;
        g_mi[st] = make_float2(m, rsqrtf(v + 1e-5f));
    }
}

// ---------------- kernel 3: sigmoid + combine ----------------
__global__ void mwn_final(float* __restrict__ out)
{
    int gi = blockIdx.x * 256 + threadIdx.x;   // < 3*S
    int beh = gi >> 18;                        // S = 2^18
    int s   = gi & (S_TOT - 1);
    float2 m1 = g_mi[beh * 2],     m3 = g_mi[beh * 2 + 1];
    float2 r1 = g_mi[6 + beh * 2], r3 = g_mi[7 + beh * 2];
    float z, w1, w3, v1, v3;
    z = (g_z[(size_t)(beh * 2)         * S_TOT + s] - m1.x) * m1.y; w1 = 1.f / (1.f + expf(-z));
    z = (g_z[(size_t)(beh * 2 + 1)     * S_TOT + s] - m3.x) * m3.y; w3 = 1.f / (1.f + expf(-z));
    z = (g_z[(size_t)(6 + beh * 2)     * S_TOT + s] - r1.x) * r1.y; v1 = 1.f / (1.f + expf(-z));
    z = (g_z[(size_t)(7 + beh * 2)     * S_TOT + s] - r3.x) * r3.y; v3 = 1.f / (1.f + expf(-z));
    out[gi]              = 0.5f * (w1 + w3);   // infoNCE weights  [0][beh][s]
    out[3 * S_TOT + gi]  = v1 + v3;            // behavior weights [1][beh][s]
}

// ---------------- launch ----------------
extern "C" void kernel_launch(void* const* d_in, const int* in_sizes, int n_in,
                              void* d_out, int out_size)
{
    const float* infoNCE = (const float*)d_in[0];
    const float* bloss   = (const float*)d_in[1];
    const int*   stepIdx = (const int*)d_in[2];
    const int*   uIdxL   = (const int*)d_in[3];
    const float* uembeds = (const float*)d_in[4];
    const float* uembed  = (const float*)d_in[5];

    prep_kernel<<<1, 256>>>(
        (const float*)d_in[6],  (const float*)d_in[7],
        (const float*)d_in[8],  (const float*)d_in[9],
        (const float*)d_in[10], (const float*)d_in[11],
        (const float*)d_in[12], (const float*)d_in[13],
        (const float*)d_in[14], (const float*)d_in[15],
        (const float*)d_in[16], (const float*)d_in[17],
        (const float*)d_in[18]);

    mwn_main<<<dim3(NBLK, 6), 256>>>(infoNCE, bloss, stepIdx, uIdxL, uembeds, uembed);
    reduce_kernel<<<12, 256>>>();
    mwn_final<<<(3 * S_TOT) / 256, 256>>>((float*)d_out);
}

// round 3
// speedup vs baseline: 1.8979x; 1.8979x over previous
#include <cuda_runtime.h>
#include <cuda_fp16.h>
#include <cstdint>
#include <cstddef>

#define S_TOT  262144
#define NBLK   2048          // S_TOT / 128
#define NUSERS 1000000
#define SQRT192 13.856406460551018f

// dynamic smem layout: sX [128][136] halves, then sB [104][136] halves
#define SX_BYTES (128 * 136 * 2)
#define SB_BYTES (104 * 136 * 2)
#define DYN_BYTES (SX_BYTES + SB_BYTES)

// ---------------- static device scratch (no cudaMalloc allowed) ----------------
__device__ __half g_BT[2][128][128];   // [type][n][k] fp16 weights (type 0=ssl,1=rs)
__device__ float  g_cvec[2][128];      // rowsum of W1[:, :64]  (loss coefficient)
__device__ float  g_bias1[2][128];
__device__ float  g_w2[2][128];
__device__ float  g_scal[6];           // b_ssl2, b_rs2, b_ssl3, b_rs3, prelu_a
__device__ float  g_z[12L * S_TOT];    // 12 pre-BN streams
__device__ float  g_psum[12 * NBLK];
__device__ float  g_psq [12 * NBLK];
__device__ float2 g_mi[12];            // (mean, inv_std) per stream

// ---------------- kernel 0: pack weights (16 blocks) ----------------
__global__ void prep_kernel(
    const float* __restrict__ Wssl1, const float* __restrict__ bssl1,
    const float* __restrict__ Wssl2, const float* __restrict__ bssl2,
    const float* __restrict__ Wssl3, const float* __restrict__ bssl3,
    const float* __restrict__ Wrs1,  const float* __restrict__ brs1,
    const float* __restrict__ Wrs2,  const float* __restrict__ brs2,
    const float* __restrict__ Wrs3,  const float* __restrict__ brs3,
    const float* __restrict__ pa)
{
    int t = threadIdx.x;
    int gt = blockIdx.x * 256 + t;
    // BT[type][n][k]: n<96 -> W1[n][64+k] ; n==96 -> z3 weight vector ; else 0
    for (int idx = gt; idx < 2 * 128 * 128; idx += 16 * 256) {
        int ty = idx >> 14;
        int n  = (idx >> 7) & 127;
        int k  = idx & 127;
        const float* W1 = ty ? Wrs1 : Wssl1;
        float v = 0.f;
        if (n < 96) {
            v = W1[n * 192 + 64 + k];
        } else if (n == 96) {
            v = ty ? ((k < 64) ? Wrs3[k] : 0.f) : Wssl3[k];
        }
        g_BT[ty][n][k] = __float2half_rn(v);
    }
    if (blockIdx.x == 0) {
        // per-column epilogue constants
        int ty = t >> 7, n = t & 127;
        const float* W1 = ty ? Wrs1 : Wssl1;
        float c = 0.f, b = 0.f, w = 0.f;
        if (n < 96) {
            for (int k = 0; k < 64; k++) c += W1[n * 192 + k];
            b = (ty ? brs1 : bssl1)[n];
            w = (ty ? Wrs2 : Wssl2)[n];
        }
        g_cvec[ty][n]  = c;
        g_bias1[ty][n] = b;
        g_w2[ty][n]    = w;
        if (t == 0) {
            g_scal[0] = bssl2[0]; g_scal[1] = brs2[0];
            g_scal[2] = bssl3[0]; g_scal[3] = brs3[0];
            g_scal[4] = pa[0];
        }
    }
}

// ---------------- kernel 1: gather + HMMA + epilogue ----------------
__global__ __launch_bounds__(256, 2)
void mwn_main(const float* __restrict__ infoNCE, const float* __restrict__ bloss,
              const int* __restrict__ stepIdx,  const int* __restrict__ uIdxList,
              const float* __restrict__ uembeds, const float* __restrict__ uembed)
{
    extern __shared__ char dyn[];
    __half* sX = (__half*)dyn;                        // [128][136]
    __half* sB = (__half*)(dyn + SX_BYTES);           // [104][136]
    __shared__ float  sLoss[128];
    __shared__ int    sIdx[128];
    __shared__ float  sC[128], sB1[128], sW2[128];
    __shared__ float  sZ1[128], sZ3[128];
    __shared__ float  sRed[16];

    const int t = threadIdx.x, lane = t & 31, w = t >> 5;
    const int combo = blockIdx.x;                     // combos adjacent -> L2 reuse
    const int type  = combo >= 3 ? 1 : 0;
    const int beh   = combo - 3 * type;
    const int s0    = blockIdx.y * 128;

    if (t < 128) {
        int s = s0 + t;
        if (type == 0) { sIdx[t] = stepIdx[s];                sLoss[t] = infoNCE[beh * S_TOT + s]; }
        else           { sIdx[t] = uIdxList[beh * S_TOT + s]; sLoss[t] = bloss[beh * S_TOT + s]; }
    } else {
        int n = t - 128;
        sC[n]  = g_cvec[type][n];
        sB1[n] = g_bias1[type][n];
        sW2[n] = g_w2[type][n];
    }
    // stage B weights into smem: rows 0..103, 128 halves each (16B chunks)
    #pragma unroll
    for (int it = 0; it < 7; ++it) {
        int idx = it * 256 + t;                       // [row(104)][seg(16)]
        if (idx < 104 * 16) {
            int row = idx >> 4, seg = idx & 15;
            *(float4*)&sB[row * 136 + seg * 8] =
                *(const float4*)&g_BT[type][row][seg * 8];
        }
    }
    __syncthreads();

    // gather: 128 rows x 128 floats; 1 warp = 1 full row per iteration
    #pragma unroll
    for (int it = 0; it < 16; ++it) {
        int lid = it * 256 + t;
        int r = lid >> 5, f = lid & 31;
        int idx = sIdx[r];
        size_t eo = ((size_t)beh * NUSERS + (size_t)idx) * 64;
        size_t uo = (size_t)idx * 64;
        const float* srcA = type ? (uembed + uo)  : (uembeds + eo);  // k 0..63
        const float* srcB = type ? (uembeds + eo) : (uembed + uo);   // k 64..127
        const float4* p = (f < 16) ? ((const float4*)srcA + f)
                                   : ((const float4*)srcB + (f - 16));
        float4 v = __ldg(p);
        int k = f * 4;
        *(__half2*)&sX[r * 136 + k]     = __floats2half2_rn(v.x, v.y);
        *(__half2*)&sX[r * 136 + k + 2] = __floats2half2_rn(v.z, v.w);
    }
    __syncthreads();

    // ---- MMA: each warp owns a 16-row slab; A (16x128) resident in registers ----
    const int g = lane >> 2, tg = lane & 3;
    uint32_t a[8][4];
    {
        uint32_t base = (uint32_t)__cvta_generic_to_shared(sX);
        int mat = lane >> 3, rowin = lane & 7;
        uint32_t arow = (uint32_t)(w * 16 + (mat & 1) * 8 + rowin);
        uint32_t aoff = base + (arow * 136 + (mat >> 1) * 8) * 2;
        #pragma unroll
        for (int ks = 0; ks < 8; ++ks) {
            asm volatile("ldmatrix.sync.aligned.m8n8.x4.shared.b16 {%0,%1,%2,%3}, [%4];"
                : "=r"(a[ks][0]), "=r"(a[ks][1]), "=r"(a[ks][2]), "=r"(a[ks][3])
                : "r"(aoff + ks * 32));
        }
    }
    const uint32_t bbase = (uint32_t)__cvta_generic_to_shared(sB)
                         + ((uint32_t)(lane & 7) * 136 + (uint32_t)(lane >> 3) * 8) * 2;
    const float l0 = sLoss[w * 16 + g], l1 = sLoss[w * 16 + 8 + g];
    const float pa = g_scal[4], b2 = g_scal[type], b3 = g_scal[2 + type];
    float zacc0 = 0.f, zacc1 = 0.f, y96a = 0.f, y96b = 0.f;

    #pragma unroll
    for (int nt = 0; nt < 13; ++nt) {
        float c0 = 0.f, c1 = 0.f, c2 = 0.f, c3 = 0.f;
        uint32_t boff = bbase + (uint32_t)(nt * 8 * 136 * 2);
        #pragma unroll
        for (int ks2 = 0; ks2 < 4; ++ks2) {
            uint32_t rb0, rb1, rb2, rb3;
            asm volatile("ldmatrix.sync.aligned.m8n8.x4.shared.b16 {%0,%1,%2,%3}, [%4];"
                : "=r"(rb0), "=r"(rb1), "=r"(rb2), "=r"(rb3)
                : "r"(boff + ks2 * 64));
            int ks = ks2 * 2;
            asm volatile("mma.sync.aligned.m16n8k16.row.col.f32.f16.f16.f32 "
                "{%0,%1,%2,%3}, {%4,%5,%6,%7}, {%8,%9}, {%0,%1,%2,%3};"
                : "+f"(c0), "+f"(c1), "+f"(c2), "+f"(c3)
                : "r"(a[ks][0]), "r"(a[ks][1]), "r"(a[ks][2]), "r"(a[ks][3]),
                  "r"(rb0), "r"(rb1));
            asm volatile("mma.sync.aligned.m16n8k16.row.col.f32.f16.f16.f32 "
                "{%0,%1,%2,%3}, {%4,%5,%6,%7}, {%8,%9}, {%0,%1,%2,%3};"
                : "+f"(c0), "+f"(c1), "+f"(c2), "+f"(c3)
                : "r"(a[ks + 1][0]), "r"(a[ks + 1][1]), "r"(a[ks + 1][2]), "r"(a[ks + 1][3]),
                  "r"(rb2), "r"(rb3));
        }
        if (nt < 12) {
            int n0 = nt * 8 + tg * 2;
            float cA = sC[n0], cB = sC[n0 + 1];
            float bA = sB1[n0], bB = sB1[n0 + 1];
            float wA = sW2[n0], wB = sW2[n0 + 1];
            float h;
            h = fmaf(l0, cA, c0) + bA; h = h >= 0.f ? h : pa * h; zacc0 = fmaf(h, wA, zacc0);
            h = fmaf(l0, cB, c1) + bB; h = h >= 0.f ? h : pa * h; zacc0 = fmaf(h, wB, zacc0);
            h = fmaf(l1, cA, c2) + bA; h = h >= 0.f ? h : pa * h; zacc1 = fmaf(h, wA, zacc1);
            h = fmaf(l1, cB, c3) + bB; h = h >= 0.f ? h : pa * h; zacc1 = fmaf(h, wB, zacc1);
        } else if (tg == 0) {
            y96a = c0;   // y[96] for row w*16+g
            y96b = c2;   // y[96] for row w*16+8+g
        }
    }
    zacc0 += __shfl_xor_sync(~0u, zacc0, 1); zacc0 += __shfl_xor_sync(~0u, zacc0, 2);
    zacc1 += __shfl_xor_sync(~0u, zacc1, 1); zacc1 += __shfl_xor_sync(~0u, zacc1, 2);
    if (tg == 0) {
        sZ1[w * 16 + g]     = SQRT192 * (zacc0 + b2);
        sZ1[w * 16 + 8 + g] = SQRT192 * (zacc1 + b2);
        float z3;
        z3 = fmaf(l0, y96a, b3); z3 = z3 >= 0.f ? z3 : pa * z3; sZ3[w * 16 + g]     = z3;
        z3 = fmaf(l1, y96b, b3); z3 = z3 >= 0.f ? z3 : pa * z3; sZ3[w * 16 + 8 + g] = z3;
    }
    __syncthreads();

    // ---- write z streams + deterministic per-block stats partials ----
    if (t < 128) {
        float z1 = sZ1[t], z3 = sZ3[t];
        int s = s0 + t;
        g_z[(size_t)(combo * 2)     * S_TOT + s] = z1;
        g_z[(size_t)(combo * 2 + 1) * S_TOT + s] = z3;
        float s1 = z1, q1 = z1 * z1, s3 = z3, q3 = z3 * z3;
        #pragma unroll
        for (int o = 16; o; o >>= 1) {
            s1 += __shfl_down_sync(~0u, s1, o); q1 += __shfl_down_sync(~0u, q1, o);
            s3 += __shfl_down_sync(~0u, s3, o); q3 += __shfl_down_sync(~0u, q3, o);
        }
        if (lane == 0) {
            sRed[w * 4]     = s1; sRed[w * 4 + 1] = q1;
            sRed[w * 4 + 2] = s3; sRed[w * 4 + 3] = q3;
        }
    }
    __syncthreads();
    if (t == 0) {
        float s1 = sRed[0] + sRed[4] + sRed[8]  + sRed[12];
        float q1 = sRed[1] + sRed[5] + sRed[9]  + sRed[13];
        float s3 = sRed[2] + sRed[6] + sRed[10] + sRed[14];
        float q3 = sRed[3] + sRed[7] + sRed[11] + sRed[15];
        int st1 = combo * 2, st3 = combo * 2 + 1;
        g_psum[st1 * NBLK + blockIdx.y] = s1; g_psq[st1 * NBLK + blockIdx.y] = q1;
        g_psum[st3 * NBLK + blockIdx.y] = s3; g_psq[st3 * NBLK + blockIdx.y] = q3;
    }
}

// ---------------- kernel 2: deterministic stats reduce ----------------
__global__ void reduce_kernel()
{
    int st = blockIdx.x, t = threadIdx.x;
    float s = 0.f, q = 0.f;
    for (int i = t; i < NBLK; i += 256) {
        s += g_psum[st * NBLK + i];
        q += g_psq [st * NBLK + i];
    }
    __shared__ float ss[256], sq[256];
    ss[t] = s; sq[t] = q;
    __syncthreads();
    for (int o = 128; o; o >>= 1) {
        if (t < o) { ss[t] += ss[t + o]; sq[t] += sq[t + o]; }
        __syncthreads();
    }
    if (t == 0) {
        float m = ss[0] / (float)S_TOT;
        float v = sq[0] / (float)S_TOT - m * m;
        if (v < 0.f) v = 0.f;
        g_mi[st] = make_float2(m, rsqrtf(v + 1e-5f));
    }
}

// ---------------- kernel 3: sigmoid + combine ----------------
__global__ void mwn_final(float* __restrict__ out)
{
    int gi = blockIdx.x * 256 + threadIdx.x;   // < 3*S
    int beh = gi >> 18;                        // S = 2^18
    int s   = gi & (S_TOT - 1);
    float2 m1 = g_mi[beh * 2],     m3 = g_mi[beh * 2 + 1];
    float2 r1 = g_mi[6 + beh * 2], r3 = g_mi[7 + beh * 2];
    float z, w1, w3, v1, v3;
    z = (g_z[(size_t)(beh * 2)         * S_TOT + s] - m1.x) * m1.y; w1 = 1.f / (1.f + expf(-z));
    z = (g_z[(size_t)(beh * 2 + 1)     * S_TOT + s] - m3.x) * m3.y; w3 = 1.f / (1.f + expf(-z));
    z = (g_z[(size_t)(6 + beh * 2)     * S_TOT + s] - r1.x) * r1.y; v1 = 1.f / (1.f + expf(-z));
    z = (g_z[(size_t)(7 + beh * 2)     * S_TOT + s] - r3.x) * r3.y; v3 = 1.f / (1.f + expf(-z));
    out[gi]              = 0.5f * (w1 + w3);   // infoNCE weights  [0][beh][s]
    out[3 * S_TOT + gi]  = v1 + v3;            // behavior weights [1][beh][s]
}

// ---------------- launch ----------------
extern "C" void kernel_launch(void* const* d_in, const int* in_sizes, int n_in,
                              void* d_out, int out_size)
{
    const float* infoNCE = (const float*)d_in[0];
    const float* bloss   = (const float*)d_in[1];
    const int*   stepIdx = (const int*)d_in[2];
    const int*   uIdxL   = (const int*)d_in[3];
    const float* uembeds = (const float*)d_in[4];
    const float* uembed  = (const float*)d_in[5];

    cudaFuncSetAttribute(mwn_main, cudaFuncAttributeMaxDynamicSharedMemorySize, DYN_BYTES);

    prep_kernel<<<16, 256>>>(
        (const float*)d_in[6],  (const float*)d_in[7],
        (const float*)d_in[8],  (const float*)d_in[9],
        (const float*)d_in[10], (const float*)d_in[11],
        (const float*)d_in[12], (const float*)d_in[13],
        (const float*)d_in[14], (const float*)d_in[15],
        (const float*)d_in[16], (const float*)d_in[17],
        (const float*)d_in[18]);

    mwn_main<<<dim3(6, NBLK), 256, DYN_BYTES>>>(infoNCE, bloss, stepIdx, uIdxL, uembeds, uembed);
    reduce_kernel<<<12, 256>>>();
    mwn_final<<<(3 * S_TOT) / 256, 256>>>((float*)d_out);
}

// round 4
// speedup vs baseline: 2.1404x; 1.1277x over previous
#include <cuda_runtime.h>
#include <cuda_fp16.h>
#include <cstdint>
#include <cstddef>

#define S_TOT  262144
#define NBLK   2048          // S_TOT / 128
#define NUSERS 1000000
#define SQRT192 13.856406460551018f

// dynamic smem: sX [128][264] halves, then sB [104][136] halves
#define XSTRIDE 264
#define SX_BYTES (128 * XSTRIDE * 2)
#define SB_BYTES (104 * 136 * 2)
#define DYN_BYTES (SX_BYTES + SB_BYTES)

// ---------------- static device scratch (no cudaMalloc allowed) ----------------
__device__ __half g_BT[2][128][128];   // [type][n][k] fp16 weights (type 0=ssl,1=rs)
__device__ float  g_cvec[2][128];      // rowsum of W1[:, :64]  (loss coefficient)
__device__ float  g_bias1[2][128];
__device__ float  g_w2[2][128];
__device__ float  g_scal[6];           // b_ssl2, b_rs2, b_ssl3, b_rs3, prelu_a
__device__ float  g_z[12L * S_TOT];    // 12 pre-BN streams
__device__ float  g_psum[12 * NBLK];
__device__ float  g_psq [12 * NBLK];
__device__ float2 g_mi[12];            // (mean, inv_std) per stream

// ---------------- kernel 0: pack weights (16 blocks) ----------------
__global__ void prep_kernel(
    const float* __restrict__ Wssl1, const float* __restrict__ bssl1,
    const float* __restrict__ Wssl2, const float* __restrict__ bssl2,
    const float* __restrict__ Wssl3, const float* __restrict__ bssl3,
    const float* __restrict__ Wrs1,  const float* __restrict__ brs1,
    const float* __restrict__ Wrs2,  const float* __restrict__ brs2,
    const float* __restrict__ Wrs3,  const float* __restrict__ brs3,
    const float* __restrict__ pa)
{
    int t = threadIdx.x;
    int gt = blockIdx.x * 256 + t;
    for (int idx = gt; idx < 2 * 128 * 128; idx += 16 * 256) {
        int ty = idx >> 14;
        int n  = (idx >> 7) & 127;
        int k  = idx & 127;
        const float* W1 = ty ? Wrs1 : Wssl1;
        float v = 0.f;
        if (n < 96) {
            v = W1[n * 192 + 64 + k];
        } else if (n == 96) {
            v = ty ? ((k < 64) ? Wrs3[k] : 0.f) : Wssl3[k];
        }
        g_BT[ty][n][k] = __float2half_rn(v);
    }
    if (blockIdx.x == 0) {
        int ty = t >> 7, n = t & 127;
        const float* W1 = ty ? Wrs1 : Wssl1;
        float c = 0.f, b = 0.f, w = 0.f;
        if (n < 96) {
            for (int k = 0; k < 64; k++) c += W1[n * 192 + k];
            b = (ty ? brs1 : bssl1)[n];
            w = (ty ? Wrs2 : Wssl2)[n];
        }
        g_cvec[ty][n]  = c;
        g_bias1[ty][n] = b;
        g_w2[ty][n]    = w;
        if (t == 0) {
            g_scal[0] = bssl2[0]; g_scal[1] = brs2[0];
            g_scal[2] = bssl3[0]; g_scal[3] = brs3[0];
            g_scal[4] = pa[0];
        }
    }
}

// ---------------- kernel 1: gather + HMMA + epilogue ----------------
// blockIdx.x == 0  : merged SSL block (3 behaviors, shared u_step gather)
// blockIdx.x == 1+b: RS block for behavior b
// sX col layout (halves): SSL: [0..63]=u_step, [64+64b .. ]=uembeds[b][step]
//                          RS: [0..63]=u_r,    [64..127]   =uembeds[beh][ridx]
__global__ __launch_bounds__(256, 2)
void mwn_main(const float* __restrict__ infoNCE, const float* __restrict__ bloss,
              const int* __restrict__ stepIdx,  const int* __restrict__ uIdxList,
              const float* __restrict__ uembeds, const float* __restrict__ uembed)
{
    extern __shared__ char dyn[];
    __half* sX = (__half*)dyn;                        // [128][264]
    __half* sB = (__half*)(dyn + SX_BYTES);           // [104][136]
    __shared__ float  sLoss[3][128];
    __shared__ int    sIdx[128];
    __shared__ float  sC[128], sB1[128], sW2[128];
    __shared__ float  sZ1[3][128], sZ3[3][128];
    __shared__ float  sRed[16];

    const int t = threadIdx.x, lane = t & 31, w = t >> 5;
    const int bx   = blockIdx.x;
    const bool ssl = (bx == 0);
    const int type = ssl ? 0 : 1;
    const int beh  = ssl ? 0 : (bx - 1);
    const int nbeh = ssl ? 3 : 1;
    const int s0   = blockIdx.y * 128;

    if (t < 128) {
        int s = s0 + t;
        if (ssl) {
            sIdx[t] = stepIdx[s];
            sLoss[0][t] = infoNCE[s];
            sLoss[1][t] = infoNCE[S_TOT + s];
            sLoss[2][t] = infoNCE[2 * S_TOT + s];
        } else {
            sIdx[t]     = uIdxList[beh * S_TOT + s];
            sLoss[0][t] = bloss[beh * S_TOT + s];
        }
    } else {
        int n = t - 128;
        sC[n]  = g_cvec[type][n];
        sB1[n] = g_bias1[type][n];
        sW2[n] = g_w2[type][n];
    }
    // stage B weights into smem
    #pragma unroll
    for (int it = 0; it < 7; ++it) {
        int idx = it * 256 + t;
        if (idx < 104 * 16) {
            int row = idx >> 4, seg = idx & 15;
            *(float4*)&sB[row * 136 + seg * 8] =
                *(const float4*)&g_BT[type][row][seg * 8];
        }
    }
    __syncthreads();

    // ---- gather ----
    if (ssl) {
        // 512 units (128 samples x 4 source rows); half-warp = one 256B row
        #pragma unroll 8
        for (int it = 0; it < 32; ++it) {
            int lid = it * 256 + t;
            int unit = lid >> 4, f = lid & 15;
            int r = unit >> 2, c = unit & 3;
            int idx = sIdx[r];
            const float4* p = (c == 0)
                ? (const float4*)(uembed + (size_t)idx * 64) + f
                : (const float4*)(uembeds + ((size_t)(c - 1) * NUSERS + (size_t)idx) * 64) + f;
            float4 v = __ldg(p);
            __half* d = &sX[r * XSTRIDE + c * 64 + f * 4];
            *(__half2*)d       = __floats2half2_rn(v.x, v.y);
            *(__half2*)(d + 2) = __floats2half2_rn(v.z, v.w);
        }
    } else {
        // 256 units (128 samples x 2 source rows)
        #pragma unroll 8
        for (int it = 0; it < 16; ++it) {
            int lid = it * 256 + t;
            int unit = lid >> 4, f = lid & 15;
            int r = unit >> 1, c = unit & 1;
            int idx = sIdx[r];
            const float4* p = (c == 0)
                ? (const float4*)(uembed + (size_t)idx * 64) + f
                : (const float4*)(uembeds + ((size_t)beh * NUSERS + (size_t)idx) * 64) + f;
            float4 v = __ldg(p);
            __half* d = &sX[r * XSTRIDE + c * 64 + f * 4];
            *(__half2*)d       = __floats2half2_rn(v.x, v.y);
            *(__half2*)(d + 2) = __floats2half2_rn(v.z, v.w);
        }
    }
    __syncthreads();

    // ---- MMA + epilogue, looped over behaviors ----
    const int g = lane >> 2, tg = lane & 3;
    const int mat = lane >> 3, rowin = lane & 7;
    const uint32_t xbase = (uint32_t)__cvta_generic_to_shared(sX);
    const uint32_t arow  = (uint32_t)(w * 16 + (mat & 1) * 8 + rowin);
    const uint32_t bbase = (uint32_t)__cvta_generic_to_shared(sB)
                         + ((uint32_t)(lane & 7) * 136 + (uint32_t)(lane >> 3) * 8) * 2;
    const float pa = g_scal[4], b2 = g_scal[type], b3 = g_scal[2 + type];

    for (int bb = 0; bb < nbeh; ++bb) {
        // A fragments: k<64 from behavior segment, k>=64 from the other segment
        uint32_t a[8][4];
        #pragma unroll
        for (int ks = 0; ks < 8; ++ks) {
            int colb;
            if (ssl) colb = (ks < 4) ? (64 + 64 * bb + 16 * ks) : (16 * (ks - 4));
            else     colb = (ks < 4) ? (16 * ks) : (64 + 16 * (ks - 4));
            uint32_t aoff = xbase + (arow * XSTRIDE + (uint32_t)colb + (uint32_t)((mat >> 1) * 8)) * 2;
            asm volatile("ldmatrix.sync.aligned.m8n8.x4.shared.b16 {%0,%1,%2,%3}, [%4];"
                : "=r"(a[ks][0]), "=r"(a[ks][1]), "=r"(a[ks][2]), "=r"(a[ks][3])
                : "r"(aoff));
        }
        const float l0 = sLoss[bb][w * 16 + g], l1 = sLoss[bb][w * 16 + 8 + g];
        float zacc0 = 0.f, zacc1 = 0.f, y96a = 0.f, y96b = 0.f;

        #pragma unroll
        for (int nt = 0; nt < 13; ++nt) {
            float c0 = 0.f, c1 = 0.f, c2 = 0.f, c3 = 0.f;
            uint32_t boff = bbase + (uint32_t)(nt * 8 * 136 * 2);
            #pragma unroll
            for (int ks2 = 0; ks2 < 4; ++ks2) {
                uint32_t rb0, rb1, rb2, rb3;
                asm volatile("ldmatrix.sync.aligned.m8n8.x4.shared.b16 {%0,%1,%2,%3}, [%4];"
                    : "=r"(rb0), "=r"(rb1), "=r"(rb2), "=r"(rb3)
                    : "r"(boff + ks2 * 64));
                int ks = ks2 * 2;
                asm volatile("mma.sync.aligned.m16n8k16.row.col.f32.f16.f16.f32 "
                    "{%0,%1,%2,%3}, {%4,%5,%6,%7}, {%8,%9}, {%0,%1,%2,%3};"
                    : "+f"(c0), "+f"(c1), "+f"(c2), "+f"(c3)
                    : "r"(a[ks][0]), "r"(a[ks][1]), "r"(a[ks][2]), "r"(a[ks][3]),
                      "r"(rb0), "r"(rb1));
                asm volatile("mma.sync.aligned.m16n8k16.row.col.f32.f16.f16.f32 "
                    "{%0,%1,%2,%3}, {%4,%5,%6,%7}, {%8,%9}, {%0,%1,%2,%3};"
                    : "+f"(c0), "+f"(c1), "+f"(c2), "+f"(c3)
                    : "r"(a[ks + 1][0]), "r"(a[ks + 1][1]), "r"(a[ks + 1][2]), "r"(a[ks + 1][3]),
                      "r"(rb2), "r"(rb3));
            }
            if (nt < 12) {
                int n0 = nt * 8 + tg * 2;
                float cA = sC[n0], cB = sC[n0 + 1];
                float bA = sB1[n0], bB = sB1[n0 + 1];
                float wA = sW2[n0], wB = sW2[n0 + 1];
                float h;
                h = fmaf(l0, cA, c0) + bA; h = h >= 0.f ? h : pa * h; zacc0 = fmaf(h, wA, zacc0);
                h = fmaf(l0, cB, c1) + bB; h = h >= 0.f ? h : pa * h; zacc0 = fmaf(h, wB, zacc0);
                h = fmaf(l1, cA, c2) + bA; h = h >= 0.f ? h : pa * h; zacc1 = fmaf(h, wA, zacc1);
                h = fmaf(l1, cB, c3) + bB; h = h >= 0.f ? h : pa * h; zacc1 = fmaf(h, wB, zacc1);
            } else if (tg == 0) {
                y96a = c0;
                y96b = c2;
            }
        }
        zacc0 += __shfl_xor_sync(~0u, zacc0, 1); zacc0 += __shfl_xor_sync(~0u, zacc0, 2);
        zacc1 += __shfl_xor_sync(~0u, zacc1, 1); zacc1 += __shfl_xor_sync(~0u, zacc1, 2);
        if (tg == 0) {
            sZ1[bb][w * 16 + g]     = SQRT192 * (zacc0 + b2);
            sZ1[bb][w * 16 + 8 + g] = SQRT192 * (zacc1 + b2);
            float z3;
            z3 = fmaf(l0, y96a, b3); z3 = z3 >= 0.f ? z3 : pa * z3; sZ3[bb][w * 16 + g]     = z3;
            z3 = fmaf(l1, y96b, b3); z3 = z3 >= 0.f ? z3 : pa * z3; sZ3[bb][w * 16 + 8 + g] = z3;
        }
    }
    __syncthreads();

    // ---- write z streams + deterministic per-block stats partials ----
    for (int bb = 0; bb < nbeh; ++bb) {
        int combo = ssl ? bb : (3 + beh);
        if (t < 128) {
            float z1 = sZ1[bb][t], z3 = sZ3[bb][t];
            int s = s0 + t;
            g_z[(size_t)(combo * 2)     * S_TOT + s] = z1;
            g_z[(size_t)(combo * 2 + 1) * S_TOT + s] = z3;
            float s1 = z1, q1 = z1 * z1, s3 = z3, q3 = z3 * z3;
            #pragma unroll
            for (int o = 16; o; o >>= 1) {
                s1 += __shfl_down_sync(~0u, s1, o); q1 += __shfl_down_sync(~0u, q1, o);
                s3 += __shfl_down_sync(~0u, s3, o); q3 += __shfl_down_sync(~0u, q3, o);
            }
            if (lane == 0) {
                sRed[w * 4]     = s1; sRed[w * 4 + 1] = q1;
                sRed[w * 4 + 2] = s3; sRed[w * 4 + 3] = q3;
            }
        }
        __syncthreads();
        if (t == 0) {
            float s1 = sRed[0] + sRed[4] + sRed[8]  + sRed[12];
            float q1 = sRed[1] + sRed[5] + sRed[9]  + sRed[13];
            float s3 = sRed[2] + sRed[6] + sRed[10] + sRed[14];
            float q3 = sRed[3] + sRed[7] + sRed[11] + sRed[15];
            int st1 = combo * 2, st3 = combo * 2 + 1;
            g_psum[st1 * NBLK + blockIdx.y] = s1; g_psq[st1 * NBLK + blockIdx.y] = q1;
            g_psum[st3 * NBLK + blockIdx.y] = s3; g_psq[st3 * NBLK + blockIdx.y] = q3;
        }
        if (bb + 1 < nbeh) __syncthreads();
    }
}

// ---------------- kernel 2: deterministic stats reduce ----------------
__global__ void reduce_kernel()
{
    int st = blockIdx.x, t = threadIdx.x;
    float s = 0.f, q = 0.f;
    for (int i = t; i < NBLK; i += 256) {
        s += g_psum[st * NBLK + i];
        q += g_psq [st * NBLK + i];
    }
    __shared__ float ss[256], sq[256];
    ss[t] = s; sq[t] = q;
    __syncthreads();
    for (int o = 128; o; o >>= 1) {
        if (t < o) { ss[t] += ss[t + o]; sq[t] += sq[t + o]; }
        __syncthreads();
    }
    if (t == 0) {
        float m = ss[0] / (float)S_TOT;
        float v = sq[0] / (float)S_TOT - m * m;
        if (v < 0.f) v = 0.f;
        g_mi[st] = make_float2(m, rsqrtf(v + 1e-5f));
    }
}

// ---------------- kernel 3: sigmoid + combine ----------------
__global__ void mwn_final(float* __restrict__ out)
{
    int gi = blockIdx.x * 256 + threadIdx.x;   // < 3*S
    int beh = gi >> 18;                        // S = 2^18
    int s   = gi & (S_TOT - 1);
    float2 m1 = g_mi[beh * 2],     m3 = g_mi[beh * 2 + 1];
    float2 r1 = g_mi[6 + beh * 2], r3 = g_mi[7 + beh * 2];
    float z, w1, w3, v1, v3;
    z = (g_z[(size_t)(beh * 2)         * S_TOT + s] - m1.x) * m1.y; w1 = 1.f / (1.f + expf(-z));
    z = (g_z[(size_t)(beh * 2 + 1)     * S_TOT + s] - m3.x) * m3.y; w3 = 1.f / (1.f + expf(-z));
    z = (g_z[(size_t)(6 + beh * 2)     * S_TOT + s] - r1.x) * r1.y; v1 = 1.f / (1.f + expf(-z));
    z = (g_z[(size_t)(7 + beh * 2)     * S_TOT + s] - r3.x) * r3.y; v3 = 1.f / (1.f + expf(-z));
    out[gi]              = 0.5f * (w1 + w3);   // infoNCE weights  [0][beh][s]
    out[3 * S_TOT + gi]  = v1 + v3;            // behavior weights [1][beh][s]
}

// ---------------- launch ----------------
extern "C" void kernel_launch(void* const* d_in, const int* in_sizes, int n_in,
                              void* d_out, int out_size)
{
    const float* infoNCE = (const float*)d_in[0];
    const float* bloss   = (const float*)d_in[1];
    const int*   stepIdx = (const int*)d_in[2];
    const int*   uIdxL   = (const int*)d_in[3];
    const float* uembeds = (const float*)d_in[4];
    const float* uembed  = (const float*)d_in[5];

    cudaFuncSetAttribute(mwn_main, cudaFuncAttributeMaxDynamicSharedMemorySize, DYN_BYTES);

    prep_kernel<<<16, 256>>>(
        (const float*)d_in[6],  (const float*)d_in[7],
        (const float*)d_in[8],  (const float*)d_in[9],
        (const float*)d_in[10], (const float*)d_in[11],
        (const float*)d_in[12], (const float*)d_in[13],
        (const float*)d_in[14], (const float*)d_in[15],
        (const float*)d_in[16], (const float*)d_in[17],
        (const float*)d_in[18]);

    mwn_main<<<dim3(4, NBLK), 256, DYN_BYTES>>>(infoNCE, bloss, stepIdx, uIdxL, uembeds, uembed);
    reduce_kernel<<<12, 256>>>();
    mwn_final<<<(3 * S_TOT) / 256, 256>>>((float*)d_out);
}

// round 6
// speedup vs baseline: 2.1909x; 1.0236x over previous
#include <cuda_runtime.h>
#include <cuda_fp16.h>
#include <cstdint>
#include <cstddef>

#define S_TOT  262144
#define NBLK   2048          // S_TOT / 128
#define NUSERS 1000000
#define SQRT192 13.856406460551018f

// dynamic smem: sX [128][264] halves, then sB [104][136] halves
#define XSTRIDE 264
#define SX_BYTES (128 * XSTRIDE * 2)
#define SB_BYTES (104 * 136 * 2)
#define DYN_BYTES (SX_BYTES + SB_BYTES)

// ---------------- static device scratch (no cudaMalloc allowed) ----------------
__device__ __half g_BT[2][128][128];   // [type][n][k] fp16 weights (type 0=ssl,1=rs)
__device__ float  g_cvec[2][128];      // rowsum of W1[:, :64]  (loss coefficient)
__device__ float  g_bias1[2][128];
__device__ float  g_w2[2][128];
__device__ float  g_scal[6];           // b_ssl2, b_rs2, b_ssl3, b_rs3, prelu_a
__device__ float  g_z[12L * S_TOT];    // 12 pre-BN streams
__device__ float  g_psum[12 * NBLK];
__device__ float  g_psq [12 * NBLK];
__device__ float2 g_mi[12];            // (mean, inv_std) per stream

// ---------------- kernel 0: pack weights (16 blocks) ----------------
__global__ void prep_kernel(
    const float* __restrict__ Wssl1, const float* __restrict__ bssl1,
    const float* __restrict__ Wssl2, const float* __restrict__ bssl2,
    const float* __restrict__ Wssl3, const float* __restrict__ bssl3,
    const float* __restrict__ Wrs1,  const float* __restrict__ brs1,
    const float* __restrict__ Wrs2,  const float* __restrict__ brs2,
    const float* __restrict__ Wrs3,  const float* __restrict__ brs3,
    const float* __restrict__ pa)
{
    int t = threadIdx.x;
    int gt = blockIdx.x * 256 + t;
    for (int idx = gt; idx < 2 * 128 * 128; idx += 16 * 256) {
        int ty = idx >> 14;
        int n  = (idx >> 7) & 127;
        int k  = idx & 127;
        const float* W1 = ty ? Wrs1 : Wssl1;
        float v = 0.f;
        if (n < 96) {
            v = W1[n * 192 + 64 + k];
        } else if (n == 96) {
            v = ty ? ((k < 64) ? Wrs3[k] : 0.f) : Wssl3[k];
        }
        g_BT[ty][n][k] = __float2half_rn(v);
    }
    if (blockIdx.x == 0) {
        int ty = t >> 7, n = t & 127;
        const float* W1 = ty ? Wrs1 : Wssl1;
        float c = 0.f, b = 0.f, w = 0.f;
        if (n < 96) {
            for (int k = 0; k < 64; k++) c += W1[n * 192 + k];
            b = (ty ? brs1 : bssl1)[n];
            w = (ty ? Wrs2 : Wssl2)[n];
        }
        g_cvec[ty][n]  = c;
        g_bias1[ty][n] = b;
        g_w2[ty][n]    = w;
        if (t == 0) {
            g_scal[0] = bssl2[0]; g_scal[1] = brs2[0];
            g_scal[2] = bssl3[0]; g_scal[3] = brs3[0];
            g_scal[4] = pa[0];
        }
    }
}

// f16-accumulator MMA helper macro (d0,d1 are uint32 holding 2 halves each)
#define MMA_F16ACC(d0, d1, a0, a1, a2, a3, b0, b1)                               \
    asm volatile("mma.sync.aligned.m16n8k16.row.col.f16.f16.f16.f16 "            \
        "{%0,%1}, {%2,%3,%4,%5}, {%6,%7}, {%0,%1};"                              \
        : "+r"(d0), "+r"(d1)                                                     \
        : "r"(a0), "r"(a1), "r"(a2), "r"(a3), "r"(b0), "r"(b1))

// ---------------- kernel 1: gather + HMMA(f16 acc, shared-K) + epilogue ----------------
// blockIdx.x == 0  : merged SSL block (3 behaviors, shared u_step gather + shared K-half GEMM)
// blockIdx.x == 1+b: RS block for behavior b
// sX cols (halves): SSL: [0..63]=u_step(shared hi-K), [64+64b..]=uembeds[b] (lo-K)
//                    RS: [0..63]=u_r (lo-K),           [64..127]=uembeds[beh] (hi-K)
__global__ __launch_bounds__(256, 2)
void mwn_main(const float* __restrict__ infoNCE, const float* __restrict__ bloss,
              const int* __restrict__ stepIdx,  const int* __restrict__ uIdxList,
              const float* __restrict__ uembeds, const float* __restrict__ uembed)
{
    extern __shared__ char dyn[];
    __half* sX = (__half*)dyn;                        // [128][264]
    __half* sB = (__half*)(dyn + SX_BYTES);           // [104][136]
    __shared__ float  sLoss[3][128];
    __shared__ int    sIdx[128];
    __shared__ float  sC[128], sB1[128], sW2[128];
    __shared__ float  sZ1[3][128], sZ3[3][128];
    __shared__ float  sRed[16];

    const int t = threadIdx.x, lane = t & 31, w = t >> 5;
    const int bx   = blockIdx.x;
    const bool ssl = (bx == 0);
    const int type = ssl ? 0 : 1;
    const int beh  = ssl ? 0 : (bx - 1);
    const int nbeh = ssl ? 3 : 1;
    const int s0   = blockIdx.y * 128;

    if (t < 128) {
        int s = s0 + t;
        if (ssl) {
            sIdx[t] = stepIdx[s];
            sLoss[0][t] = infoNCE[s];
            sLoss[1][t] = infoNCE[S_TOT + s];
            sLoss[2][t] = infoNCE[2 * S_TOT + s];
        } else {
            sIdx[t]     = uIdxList[beh * S_TOT + s];
            sLoss[0][t] = bloss[beh * S_TOT + s];
        }
    } else {
        int n = t - 128;
        sC[n]  = g_cvec[type][n];
        sB1[n] = g_bias1[type][n];
        sW2[n] = g_w2[type][n];
    }
    // stage B weights into smem
    #pragma unroll
    for (int it = 0; it < 7; ++it) {
        int idx = it * 256 + t;
        if (idx < 104 * 16) {
            int row = idx >> 4, seg = idx & 15;
            *(float4*)&sB[row * 136 + seg * 8] =
                *(const float4*)&g_BT[type][row][seg * 8];
        }
    }
    __syncthreads();

    // ---- gather ----
    if (ssl) {
        #pragma unroll 8
        for (int it = 0; it < 32; ++it) {
            int lid = it * 256 + t;
            int unit = lid >> 4, f = lid & 15;
            int r = unit >> 2, c = unit & 3;
            int idx = sIdx[r];
            const float4* p = (c == 0)
                ? (const float4*)(uembed + (size_t)idx * 64) + f
                : (const float4*)(uembeds + ((size_t)(c - 1) * NUSERS + (size_t)idx) * 64) + f;
            float4 v = __ldg(p);
            __half* d = &sX[r * XSTRIDE + c * 64 + f * 4];
            *(__half2*)d       = __floats2half2_rn(v.x, v.y);
            *(__half2*)(d + 2) = __floats2half2_rn(v.z, v.w);
        }
    } else {
        #pragma unroll 8
        for (int it = 0; it < 16; ++it) {
            int lid = it * 256 + t;
            int unit = lid >> 4, f = lid & 15;
            int r = unit >> 1, c = unit & 1;
            int idx = sIdx[r];
            const float4* p = (c == 0)
                ? (const float4*)(uembed + (size_t)idx * 64) + f
                : (const float4*)(uembeds + ((size_t)beh * NUSERS + (size_t)idx) * 64) + f;
            float4 v = __ldg(p);
            __half* d = &sX[r * XSTRIDE + c * 64 + f * 4];
            *(__half2*)d       = __floats2half2_rn(v.x, v.y);
            *(__half2*)(d + 2) = __floats2half2_rn(v.z, v.w);
        }
    }
    __syncthreads();

    // ---- MMA ----
    const int g = lane >> 2, tg = lane & 3;
    const int mat = lane >> 3, rowin = lane & 7;
    const uint32_t xbase = (uint32_t)__cvta_generic_to_shared(sX);
    const uint32_t arow  = (uint32_t)(w * 16 + (mat & 1) * 8 + rowin);
    const uint32_t bbase = (uint32_t)__cvta_generic_to_shared(sB)
                         + ((uint32_t)(lane & 7) * 136 + (uint32_t)(lane >> 3) * 8) * 2;
    const float pa = g_scal[4], b2 = g_scal[type], b3 = g_scal[2 + type];

    // hi-K A fragments (GEMM k 64..127): SSL = u_step (shared!), RS = ue
    uint32_t ah[4][4];
    #pragma unroll
    for (int ks2 = 0; ks2 < 4; ++ks2) {
        int colb = ssl ? (16 * ks2) : (64 + 16 * ks2);
        uint32_t aoff = xbase + (arow * XSTRIDE + (uint32_t)colb + (uint32_t)((mat >> 1) * 8)) * 2;
        asm volatile("ldmatrix.sync.aligned.m8n8.x4.shared.b16 {%0,%1,%2,%3}, [%4];"
            : "=r"(ah[ks2][0]), "=r"(ah[ks2][1]), "=r"(ah[ks2][2]), "=r"(ah[ks2][3])
            : "r"(aoff));
    }
    // shared hi-K partial accumulators (f16x2): one per n-tile
    uint32_t csh[13][2];
    #pragma unroll
    for (int nt = 0; nt < 13; ++nt) {
        uint32_t d0 = 0, d1 = 0;
        uint32_t boff = bbase + (uint32_t)(nt * 8 * 136 * 2);
        #pragma unroll
        for (int ks2 = 2; ks2 < 4; ++ks2) {
            uint32_t rb0, rb1, rb2, rb3;
            asm volatile("ldmatrix.sync.aligned.m8n8.x4.shared.b16 {%0,%1,%2,%3}, [%4];"
                : "=r"(rb0), "=r"(rb1), "=r"(rb2), "=r"(rb3)
                : "r"(boff + ks2 * 64));
            int i = (ks2 - 2) * 2;
            MMA_F16ACC(d0, d1, ah[i][0],     ah[i][1],     ah[i][2],     ah[i][3],     rb0, rb1);
            MMA_F16ACC(d0, d1, ah[i + 1][0], ah[i + 1][1], ah[i + 1][2], ah[i + 1][3], rb2, rb3);
        }
        csh[nt][0] = d0; csh[nt][1] = d1;
    }

    for (int bb = 0; bb < nbeh; ++bb) {
        // lo-K A fragments (GEMM k 0..63): SSL = ue_bb, RS = u_r
        uint32_t al[4][4];
        #pragma unroll
        for (int ks2 = 0; ks2 < 4; ++ks2) {
            int colb = ssl ? (64 + 64 * bb + 16 * ks2) : (16 * ks2);
            uint32_t aoff = xbase + (arow * XSTRIDE + (uint32_t)colb + (uint32_t)((mat >> 1) * 8)) * 2;
            asm volatile("ldmatrix.sync.aligned.m8n8.x4.shared.b16 {%0,%1,%2,%3}, [%4];"
                : "=r"(al[ks2][0]), "=r"(al[ks2][1]), "=r"(al[ks2][2]), "=r"(al[ks2][3])
                : "r"(aoff));
        }
        const float l0 = sLoss[bb][w * 16 + g], l1 = sLoss[bb][w * 16 + 8 + g];
        float zacc0 = 0.f, zacc1 = 0.f, y96a = 0.f, y96b = 0.f;

        #pragma unroll
        for (int nt = 0; nt < 13; ++nt) {
            uint32_t d0 = csh[nt][0], d1 = csh[nt][1];
            uint32_t boff = bbase + (uint32_t)(nt * 8 * 136 * 2);
            #pragma unroll
            for (int ks2 = 0; ks2 < 2; ++ks2) {
                uint32_t rb0, rb1, rb2, rb3;
                asm volatile("ldmatrix.sync.aligned.m8n8.x4.shared.b16 {%0,%1,%2,%3}, [%4];"
                    : "=r"(rb0), "=r"(rb1), "=r"(rb2), "=r"(rb3)
                    : "r"(boff + ks2 * 64));
                int i = ks2 * 2;
                MMA_F16ACC(d0, d1, al[i][0],     al[i][1],     al[i][2],     al[i][3],     rb0, rb1);
                MMA_F16ACC(d0, d1, al[i + 1][0], al[i + 1][1], al[i + 1][2], al[i + 1][3], rb2, rb3);
            }
            __half2 h0 = *(__half2*)&d0;   // row g    : cols n0, n0+1
            __half2 h1 = *(__half2*)&d1;   // row g+8  : cols n0, n0+1
            if (nt < 12) {
                int n0 = nt * 8 + tg * 2;
                float cA = sC[n0], cB = sC[n0 + 1];
                float bA = sB1[n0], bB = sB1[n0 + 1];
                float wA = sW2[n0], wB = sW2[n0 + 1];
                float c0 = __low2float(h0), c1 = __high2float(h0);
                float c2 = __low2float(h1), c3 = __high2float(h1);
                float h;
                h = fmaf(l0, cA, c0) + bA; h = h >= 0.f ? h : pa * h; zacc0 = fmaf(h, wA, zacc0);
                h = fmaf(l0, cB, c1) + bB; h = h >= 0.f ? h : pa * h; zacc0 = fmaf(h, wB, zacc0);
                h = fmaf(l1, cA, c2) + bA; h = h >= 0.f ? h : pa * h; zacc1 = fmaf(h, wA, zacc1);
                h = fmaf(l1, cB, c3) + bB; h = h >= 0.f ? h : pa * h; zacc1 = fmaf(h, wB, zacc1);
            } else if (tg == 0) {
                y96a = __low2float(h0);
                y96b = __low2float(h1);
            }
        }
        zacc0 += __shfl_xor_sync(~0u, zacc0, 1); zacc0 += __shfl_xor_sync(~0u, zacc0, 2);
        zacc1 += __shfl_xor_sync(~0u, zacc1, 1); zacc1 += __shfl_xor_sync(~0u, zacc1, 2);
        if (tg == 0) {
            sZ1[bb][w * 16 + g]     = SQRT192 * (zacc0 + b2);
            sZ1[bb][w * 16 + 8 + g] = SQRT192 * (zacc1 + b2);
            float z3;
            z3 = fmaf(l0, y96a, b3); z3 = z3 >= 0.f ? z3 : pa * z3; sZ3[bb][w * 16 + g]     = z3;
            z3 = fmaf(l1, y96b, b3); z3 = z3 >= 0.f ? z3 : pa * z3; sZ3[bb][w * 16 + 8 + g] = z3;
        }
    }
    __syncthreads();

    // ---- write z streams + deterministic per-block stats partials ----
    for (int bb = 0; bb < nbeh; ++bb) {
        int combo = ssl ? bb : (3 + beh);
        if (t < 128) {
            float z1 = sZ1[bb][t], z3 = sZ3[bb][t];
            int s = s0 + t;
            g_z[(size_t)(combo * 2)     * S_TOT + s] = z1;
            g_z[(size_t)(combo * 2 + 1) * S_TOT + s] = z3;
            float s1 = z1, q1 = z1 * z1, s3 = z3, q3 = z3 * z3;
            #pragma unroll
            for (int o = 16; o; o >>= 1) {
                s1 += __shfl_down_sync(~0u, s1, o); q1 += __shfl_down_sync(~0u, q1, o);
                s3 += __shfl_down_sync(~0u, s3, o); q3 += __shfl_down_sync(~0u, q3, o);
            }
            if (lane == 0) {
                sRed[w * 4]     = s1; sRed[w * 4 + 1] = q1;
                sRed[w * 4 + 2] = s3; sRed[w * 4 + 3] = q3;
            }
        }
        __syncthreads();
        if (t == 0) {
            float s1 = sRed[0] + sRed[4] + sRed[8]  + sRed[12];
            float q1 = sRed[1] + sRed[5] + sRed[9]  + sRed[13];
            float s3 = sRed[2] + sRed[6] + sRed[10] + sRed[14];
            float q3 = sRed[3] + sRed[7] + sRed[11] + sRed[15];
            int st1 = combo * 2, st3 = combo * 2 + 1;
            g_psum[st1 * NBLK + blockIdx.y] = s1; g_psq[st1 * NBLK + blockIdx.y] = q1;
            g_psum[st3 * NBLK + blockIdx.y] = s3; g_psq[st3 * NBLK + blockIdx.y] = q3;
        }
        if (bb + 1 < nbeh) __syncthreads();
    }
}

// ---------------- kernel 2: deterministic stats reduce ----------------
__global__ void reduce_kernel()
{
    int st = blockIdx.x, t = threadIdx.x;
    float s = 0.f, q = 0.f;
    for (int i = t; i < NBLK; i += 256) {
        s += g_psum[st * NBLK + i];
        q += g_psq [st * NBLK + i];
    }
    __shared__ float ss[256], sq[256];
    ss[t] = s; sq[t] = q;
    __syncthreads();
    for (int o = 128; o; o >>= 1) {
        if (t < o) { ss[t] += ss[t + o]; sq[t] += sq[t + o]; }
        __syncthreads();
    }
    if (t == 0) {
        float m = ss[0] / (float)S_TOT;
        float v = sq[0] / (float)S_TOT - m * m;
        if (v < 0.f) v = 0.f;
        g_mi[st] = make_float2(m, rsqrtf(v + 1e-5f));
    }
}

// ---------------- kernel 3: sigmoid + combine ----------------
__global__ void mwn_final(float* __restrict__ out)
{
    int gi = blockIdx.x * 256 + threadIdx.x;   // < 3*S
    int beh = gi >> 18;                        // S = 2^18
    int s   = gi & (S_TOT - 1);
    float2 m1 = g_mi[beh * 2],     m3 = g_mi[beh * 2 + 1];
    float2 r1 = g_mi[6 + beh * 2], r3 = g_mi[7 + beh * 2];
    float z, w1, w3, v1, v3;
    z = (g_z[(size_t)(beh * 2)     * S_TOT + s] - m1.x) * m1.y; w1 = 1.f / (1.f + expf(-z));
    z = (g_z[(size_t)(beh * 2 + 1) * S_TOT + s] - m3.x) * m3.y; w3 = 1.f / (1.f + expf(-z));
    z = (g_z[(size_t)(6 + beh * 2) * S_TOT + s] - r1.x) * r1.y; v1 = 1.f / (1.f + expf(-z));
    z = (g_z[(size_t)(7 + beh * 2) * S_TOT + s] - r3.x) * r3.y; v3 = 1.f / (1.f + expf(-z));
    out[gi]             = 0.5f * (w1 + w3);
    out[3 * S_TOT + gi] = v1 + v3;
}

// ---------------- launch ----------------
extern "C" void kernel_launch(void* const* d_in, const int* in_sizes, int n_in,
                              void* d_out, int out_size)
{
    const float* infoNCE = (const float*)d_in[0];
    const float* bloss   = (const float*)d_in[1];
    const int*   stepIdx = (const int*)d_in[2];
    const int*   uIdxL   = (const int*)d_in[3];
    const float* uembeds = (const float*)d_in[4];
    const float* uembed  = (const float*)d_in[5];

    cudaFuncSetAttribute(mwn_main, cudaFuncAttributeMaxDynamicSharedMemorySize, DYN_BYTES);

    prep_kernel<<<16, 256>>>(
        (const float*)d_in[6],  (const float*)d_in[7],
        (const float*)d_in[8],  (const float*)d_in[9],
        (const float*)d_in[10], (const float*)d_in[11],
        (const float*)d_in[12], (const float*)d_in[13],
        (const float*)d_in[14], (const float*)d_in[15],
        (const float*)d_in[16], (const float*)d_in[17],
        (const float*)d_in[18]);

    mwn_main<<<dim3(4, NBLK), 256, DYN_BYTES>>>(infoNCE, bloss, stepIdx, uIdxL, uembeds, uembed);
    reduce_kernel<<<12, 256>>>();
    mwn_final<<<(3 * S_TOT) / 256, 256>>>((float*)d_out);
}